// round 15
// baseline (speedup 1.0000x reference)
#include <cuda_runtime.h>
#include <math.h>

#define NT 64
#define NH 2048
#define NI 1408
#define NE 32
#define NK 4
#define NPAIR (NT * NK)
#define MAXSLOT (NPAIR + NE * 7)   // per-expert padding to multiple of 8
#define MAXCHUNK 64                // sum ceil(cnt_e/8) <= 256/8 + 32

// ---- scratch (device globals: no allocation allowed) ----
__device__ int   d_expert_count[NE];
__device__ int   d_expert_start[NE];
__device__ int   d_nchunks;
__device__ int   d_chunk_slot0[MAXCHUNK];   // chunk -> first slot (mult of 8 within region)
__device__ int   d_chunk_nc[MAXCHUNK];      // chunk -> live token count (1..8)
__device__ int   d_chunk_expert[MAXCHUNK];  // chunk -> expert
__device__ int   d_pair_token[MAXSLOT];     // slot -> token (pads -> 0)
__device__ int   d_pair_idx[NT * NK];       // (token,k) -> slot
__device__ float d_topk_w[NT * NK];         // routing weights
__device__ float d_mixed[MAXSLOT * NI];     // silu(g)*u per slot (plain layout)
__device__ float d_pair_out[MAXSLOT * NH];  // down output per slot

// ---- packed f32x2 helpers (FFMA2: PTX-only on sm_103a) ----
__device__ __forceinline__ unsigned long long fma2(unsigned long long a,
                                                   unsigned long long b,
                                                   unsigned long long c) {
    unsigned long long d;
    asm("fma.rn.f32x2 %0, %1, %2, %3;" : "=l"(d) : "l"(a), "l"(b), "l"(c));
    return d;
}
__device__ __forceinline__ unsigned long long add2(unsigned long long a,
                                                   unsigned long long b) {
    unsigned long long d;
    asm("add.rn.f32x2 %0, %1, %2;" : "=l"(d) : "l"(a), "l"(b));
    return d;
}
// warp-reduce packed accumulator, fold (even-k, odd-k) halves at the end
__device__ __forceinline__ float wred(unsigned long long v) {
#pragma unroll
    for (int o = 16; o > 0; o >>= 1)
        v = add2(v, __shfl_down_sync(0xFFFFFFFFu, v, o));
    float lo, hi;
    asm("mov.b64 {%0, %1}, %2;" : "=f"(lo), "=f"(hi) : "l"(v));
    return lo + hi;
}
// streaming 16B load (evict-first: weights must not thrash L1)
__device__ __forceinline__ ulonglong2 ldcsu2(const ulonglong2* p) {
    ulonglong2 v;
    asm("ld.global.cs.v2.u64 {%0, %1}, [%2];" : "=l"(v.x), "=l"(v.y) : "l"(p));
    return v;
}

// ============================================================
// Kernel 1: routing + chunk table. One block, one thread/token.
// ============================================================
__global__ void route_kernel(const float* __restrict__ logits) {
    __shared__ int s_count[NE];
    __shared__ int s_start[NE];
    __shared__ int s_slot[NE];
    const int t = threadIdx.x;

    if (t < NE) { s_count[t] = 0; s_slot[t] = 0; }
    __syncthreads();

    float v[NE];
#pragma unroll
    for (int e = 0; e < NE; e++) v[e] = logits[t * NE + e];

    int ids[NK];
    float vals[NK];
#pragma unroll
    for (int k = 0; k < NK; k++) {
        int best = 0;
        float bv = -1e30f;
#pragma unroll
        for (int e = 0; e < NE; e++) {
            if (v[e] > bv) { bv = v[e]; best = e; }  // strict > : lowest index wins ties
        }
        ids[k] = best;
        vals[k] = bv;
        v[best] = -1e30f;
    }

    float m = vals[0];
    float w[NK];
    float s = 0.f;
#pragma unroll
    for (int k = 0; k < NK; k++) { w[k] = expf(vals[k] - m); s += w[k]; }
    float inv = 1.f / s;
#pragma unroll
    for (int k = 0; k < NK; k++) d_topk_w[t * NK + k] = w[k] * inv;

#pragma unroll
    for (int k = 0; k < NK; k++) atomicAdd(&s_count[ids[k]], 1);
    __syncthreads();

    if (t == 0) {
        int off = 0;
        int nch = 0;
        for (int e = 0; e < NE; e++) {
            s_start[e] = off;
            const int cnt = s_count[e];
            for (int c = 0; c < cnt; c += 8) {
                d_chunk_slot0[nch] = off + c;
                d_chunk_nc[nch] = (cnt - c < 8) ? (cnt - c) : 8;
                d_chunk_expert[nch] = e;
                nch++;
            }
            off += (cnt + 7) & ~7;   // pad each expert region to multiple of 8
        }
        d_nchunks = nch;
    }
    __syncthreads();

#pragma unroll
    for (int k = 0; k < NK; k++) {
        int slot = atomicAdd(&s_slot[ids[k]], 1);
        int p = s_start[ids[k]] + slot;
        d_pair_token[p] = t;
        d_pair_idx[t * NK + k] = p;
    }
    if (t < NE) {
        d_expert_count[t] = s_count[t];
        d_expert_start[t] = s_start[t];
        const int cnt = s_count[t];
        const int padded = (cnt + 7) & ~7;
        for (int p = cnt; p < padded; p++)      // pad slots -> token 0
            d_pair_token[s_start[t] + p] = 0;
    }
}

// ============================================================
// Kernel 2: gate/up matvecs + SiLU.
// One block = one chunk x 8 inter rows. Stage the chunk's 8
// (gathered) x rows into SMEM once; mainloop global loads are
// ONLY the 4 weight streams (dense LDG.128, evict-first).
// FFMA2 halves = (k,k+1): zero movs, conflict-free LDS.128.
// ============================================================
__global__ void __launch_bounds__(128) gateup_kernel(
    const float* __restrict__ x,
    const float* __restrict__ w_gate, const float* __restrict__ w_up)
{
    extern __shared__ float sx[];   // 8 * NH floats = 64 KB
    const int ch = blockIdx.y;
    if (ch >= d_nchunks) return;
    const int slot0 = d_chunk_slot0[ch];
    const int nc = d_chunk_nc[ch];
    const int e = d_chunk_expert[ch];

    const int tid = threadIdx.x;
    const int warp = tid >> 5;
    const int lane = tid & 31;
    const int i0 = blockIdx.x * 8 + warp * 2;   // 2 inter rows per warp

    // ---- stage 8 token rows (gather while staging) ----
#pragma unroll
    for (int q = 0; q < 8 * NH / 4 / 128; q++) {   // 32 float4 per thread
        const int idx = tid + q * 128;
        const int tr = idx >> 9;                   // token row 0..7
        const int kk = idx & 511;
        const int tok = d_pair_token[slot0 + tr];
        ((float4*)sx)[idx] = __ldg((const float4*)(x + (size_t)tok * NH) + kk);
    }
    __syncthreads();

    const ulonglong2* __restrict__ G0 = (const ulonglong2*)(w_gate + ((size_t)e * NI + i0) * NH);
    const ulonglong2* __restrict__ G1 = G0 + NH / 4;
    const ulonglong2* __restrict__ U0 = (const ulonglong2*)(w_up + ((size_t)e * NI + i0) * NH);
    const ulonglong2* __restrict__ U1 = U0 + NH / 4;

    unsigned long long ag0[8], ag1[8], au0[8], au1[8];
#pragma unroll
    for (int t = 0; t < 8; t++) { ag0[t] = 0ull; ag1[t] = 0ull; au0[t] = 0ull; au1[t] = 0ull; }

    constexpr int ITERS = NH / 4 / 32;   // 16
#pragma unroll 2
    for (int it = 0; it < ITERS; it++) {
        const int kq = lane + 32 * it;           // covers k = 4kq..4kq+3
        const ulonglong2 a0 = ldcsu2(&G0[kq]);
        const ulonglong2 a1 = ldcsu2(&G1[kq]);
        const ulonglong2 b0 = ldcsu2(&U0[kq]);
        const ulonglong2 b1 = ldcsu2(&U1[kq]);
#pragma unroll
        for (int t = 0; t < 8; t++) {
            const ulonglong2 xv = *(const ulonglong2*)(sx + (size_t)t * NH + 4 * kq);
            ag0[t] = fma2(a0.x, xv.x, ag0[t]); ag0[t] = fma2(a0.y, xv.y, ag0[t]);
            ag1[t] = fma2(a1.x, xv.x, ag1[t]); ag1[t] = fma2(a1.y, xv.y, ag1[t]);
            au0[t] = fma2(b0.x, xv.x, au0[t]); au0[t] = fma2(b0.y, xv.y, au0[t]);
            au1[t] = fma2(b1.x, xv.x, au1[t]); au1[t] = fma2(b1.y, xv.y, au1[t]);
        }
    }

#pragma unroll
    for (int t = 0; t < 8; t++) {
        const float g0 = wred(ag0[t]);
        const float g1 = wred(ag1[t]);
        const float u0 = wred(au0[t]);
        const float u1 = wred(au1[t]);
        if (lane == 0 && t < nc) {
            float* mo = d_mixed + (size_t)(slot0 + t) * NI + i0;
            mo[0] = (g0 / (1.f + expf(-g0))) * u0;
            mo[1] = (g1 / (1.f + expf(-g1))) * u1;
        }
    }
}

// ============================================================
// Kernel 3: down projection.
// One block = one chunk x 16 hidden rows. Stage the chunk's 8
// contiguous mixed rows (45 KB static SMEM); warp = 4 h-rows x
// 8 tokens.
// ============================================================
__global__ void __launch_bounds__(128) down_kernel(const float* __restrict__ w_down)
{
    __shared__ float sm[8 * NI];   // 45 KB
    const int ch = blockIdx.y;
    if (ch >= d_nchunks) return;
    const int slot0 = d_chunk_slot0[ch];
    const int nc = d_chunk_nc[ch];
    const int e = d_chunk_expert[ch];

    const int tid = threadIdx.x;
    const int warp = tid >> 5;
    const int lane = tid & 31;
    const int h0 = blockIdx.x * 16 + warp * 4;   // 4 hidden rows per warp

    // ---- stage 8 mixed rows (contiguous slots; pads carry finite garbage, discarded) ----
    {
        const float4* __restrict__ src = (const float4*)(d_mixed + (size_t)slot0 * NI);
#pragma unroll
        for (int q = 0; q < 8 * NI / 4 / 128; q++) {   // 22 float4 per thread
            const int idx = tid + q * 128;
            ((float4*)sm)[idx] = __ldg(&src[idx]);
        }
    }
    __syncthreads();

    const ulonglong2* __restrict__ R0 = (const ulonglong2*)(w_down + ((size_t)e * NH + h0) * NI);
    const ulonglong2* __restrict__ R1 = R0 + NI / 4;
    const ulonglong2* __restrict__ R2 = R0 + 2 * (NI / 4);
    const ulonglong2* __restrict__ R3 = R0 + 3 * (NI / 4);

    unsigned long long a0[8], a1[8], a2[8], a3[8];
#pragma unroll
    for (int t = 0; t < 8; t++) { a0[t] = 0ull; a1[t] = 0ull; a2[t] = 0ull; a3[t] = 0ull; }

    constexpr int ITERS = NI / 4 / 32;   // 11
#pragma unroll 2
    for (int it = 0; it < ITERS; it++) {
        const int kq = lane + 32 * it;
        const ulonglong2 w0 = ldcsu2(&R0[kq]);
        const ulonglong2 w1 = ldcsu2(&R1[kq]);
        const ulonglong2 w2 = ldcsu2(&R2[kq]);
        const ulonglong2 w3 = ldcsu2(&R3[kq]);
#pragma unroll
        for (int t = 0; t < 8; t++) {
            const ulonglong2 xv = *(const ulonglong2*)(sm + (size_t)t * NI + 4 * kq);
            a0[t] = fma2(w0.x, xv.x, a0[t]); a0[t] = fma2(w0.y, xv.y, a0[t]);
            a1[t] = fma2(w1.x, xv.x, a1[t]); a1[t] = fma2(w1.y, xv.y, a1[t]);
            a2[t] = fma2(w2.x, xv.x, a2[t]); a2[t] = fma2(w2.y, xv.y, a2[t]);
            a3[t] = fma2(w3.x, xv.x, a3[t]); a3[t] = fma2(w3.y, xv.y, a3[t]);
        }
    }

#pragma unroll
    for (int t = 0; t < 8; t++) {
        const float v0 = wred(a0[t]);
        const float v1 = wred(a1[t]);
        const float v2 = wred(a2[t]);
        const float v3 = wred(a3[t]);
        if (lane == 0 && t < nc) {
            float* po = d_pair_out + (size_t)(slot0 + t) * NH + h0;
            po[0] = v0; po[1] = v1; po[2] = v2; po[3] = v3;
        }
    }
}

// ============================================================
// Kernel 4: weighted combine of the 4 routed pair outputs.
// ============================================================
__global__ void combine_kernel(float* __restrict__ out)
{
    const int idx = blockIdx.x * blockDim.x + threadIdx.x;  // [0, NT*NH)
    const int t = idx / NH;
    const int h = idx - t * NH;
    float s = 0.f;
#pragma unroll
    for (int k = 0; k < NK; k++) {
        const int p = d_pair_idx[t * NK + k];
        s = fmaf(d_topk_w[t * NK + k], d_pair_out[(size_t)p * NH + h], s);
    }
    out[idx] = s;
}

// ============================================================
extern "C" void kernel_launch(void* const* d_in, const int* in_sizes, int n_in,
                              void* d_out, int out_size)
{
    const float* x      = (const float*)d_in[0];
    const float* logits = (const float*)d_in[1];
    const float* wg     = (const float*)d_in[2];
    const float* wu     = (const float*)d_in[3];
    const float* wd     = (const float*)d_in[4];
    float* out = (float*)d_out;

    static bool attr_set = false;
    if (!attr_set) {
        cudaFuncSetAttribute(gateup_kernel,
                             cudaFuncAttributeMaxDynamicSharedMemorySize,
                             8 * NH * sizeof(float));
        attr_set = true;
    }

    route_kernel<<<1, NT>>>(logits);
    gateup_kernel<<<dim3(NI / 8, MAXCHUNK), 128, 8 * NH * sizeof(float)>>>(x, wg, wu);
    down_kernel<<<dim3(NH / 16, MAXCHUNK), 128>>>(wd);
    combine_kernel<<<(NT * NH) / 256, 256>>>(out);
}

// round 16
// speedup vs baseline: 1.2014x; 1.2014x over previous
#include <cuda_runtime.h>
#include <math.h>
#include <stdint.h>

#define NT 64
#define NH 2048
#define NI 1408
#define NE 32
#define NK 4
#define NPAIR (NT * NK)
#define MAXSLOT (NPAIR + NE * 7)   // per-expert padding to multiple of 8
#define MAXCHUNK 64

// ---- scratch (device globals: no allocation allowed) ----
__device__ int   d_nchunks;
__device__ int   d_chunk_slot0[MAXCHUNK];   // chunk -> first slot
__device__ int   d_chunk_nc[MAXCHUNK];      // chunk -> live token count (1..8)
__device__ int   d_chunk_expert[MAXCHUNK];  // chunk -> expert
__device__ int   d_pair_token[MAXSLOT];     // slot -> token (pads -> 0)
__device__ int   d_pair_idx[NT * NK];       // (token,k) -> slot
__device__ float d_topk_w[NT * NK];         // routing weights
__device__ float d_mixed[MAXSLOT * NI];     // silu(g)*u per slot
__device__ float d_pair_out[MAXSLOT * NH];  // down output per slot

// ---- packed f32x2 helpers (FFMA2: PTX-only on sm_103a) ----
__device__ __forceinline__ unsigned long long fma2(unsigned long long a,
                                                   unsigned long long b,
                                                   unsigned long long c) {
    unsigned long long d;
    asm("fma.rn.f32x2 %0, %1, %2, %3;" : "=l"(d) : "l"(a), "l"(b), "l"(c));
    return d;
}
__device__ __forceinline__ unsigned long long add2(unsigned long long a,
                                                   unsigned long long b) {
    unsigned long long d;
    asm("add.rn.f32x2 %0, %1, %2;" : "=l"(d) : "l"(a), "l"(b));
    return d;
}
// warp-reduce packed accumulator, fold (k,k+1) halves at the end
__device__ __forceinline__ float wred(unsigned long long v) {
#pragma unroll
    for (int o = 16; o > 0; o >>= 1)
        v = add2(v, __shfl_down_sync(0xFFFFFFFFu, v, o));
    float lo, hi;
    asm("mov.b64 {%0, %1}, %2;" : "=f"(lo), "=f"(hi) : "l"(v));
    return lo + hi;
}
// 16-byte async copy global -> shared (no register staging)
__device__ __forceinline__ void cpa16(uint32_t dst, const float* src) {
    asm volatile("cp.async.cg.shared.global [%0], [%1], 16;" :: "r"(dst), "l"(src));
}

// ============================================================
// Kernel 1: routing + chunk table. One block, one thread/token.
// ============================================================
__global__ void route_kernel(const float* __restrict__ logits) {
    __shared__ int s_count[NE];
    __shared__ int s_start[NE];
    __shared__ int s_slot[NE];
    const int t = threadIdx.x;

    if (t < NE) { s_count[t] = 0; s_slot[t] = 0; }
    __syncthreads();

    float v[NE];
#pragma unroll
    for (int e = 0; e < NE; e++) v[e] = logits[t * NE + e];

    int ids[NK];
    float vals[NK];
#pragma unroll
    for (int k = 0; k < NK; k++) {
        int best = 0;
        float bv = -1e30f;
#pragma unroll
        for (int e = 0; e < NE; e++) {
            if (v[e] > bv) { bv = v[e]; best = e; }  // strict > : lowest index wins ties
        }
        ids[k] = best;
        vals[k] = bv;
        v[best] = -1e30f;
    }

    float m = vals[0];
    float w[NK];
    float s = 0.f;
#pragma unroll
    for (int k = 0; k < NK; k++) { w[k] = expf(vals[k] - m); s += w[k]; }
    float inv = 1.f / s;
#pragma unroll
    for (int k = 0; k < NK; k++) d_topk_w[t * NK + k] = w[k] * inv;

#pragma unroll
    for (int k = 0; k < NK; k++) atomicAdd(&s_count[ids[k]], 1);
    __syncthreads();

    if (t == 0) {
        int off = 0;
        int nch = 0;
        for (int e = 0; e < NE; e++) {
            s_start[e] = off;
            const int cnt = s_count[e];
            for (int c = 0; c < cnt; c += 8) {
                d_chunk_slot0[nch] = off + c;
                d_chunk_nc[nch] = (cnt - c < 8) ? (cnt - c) : 8;
                d_chunk_expert[nch] = e;
                nch++;
            }
            off += (cnt + 7) & ~7;   // pad each expert region to multiple of 8
        }
        d_nchunks = nch;
    }
    __syncthreads();

#pragma unroll
    for (int k = 0; k < NK; k++) {
        int slot = atomicAdd(&s_slot[ids[k]], 1);
        int p = s_start[ids[k]] + slot;
        d_pair_token[p] = t;
        d_pair_idx[t * NK + k] = p;
    }
    if (t < NE) {
        const int cnt = s_count[t];
        const int padded = (cnt + 7) & ~7;
        for (int p = cnt; p < padded; p++)      // pad slots -> token 0
            d_pair_token[s_start[t] + p] = 0;
    }
}

// ============================================================
// Kernel 2: gate/up matvecs + SiLU.
// Block = one chunk x 8 inter rows. cp.async double-buffered
// k-tiles (KTILE=256 floats): 16 weight rows (8 gate + 8 up)
// + 8 gathered x rows per stage. Warp computes 2 inter rows
// (gate+up) x 8 tokens from SMEM; FFMA2 halves = (k,k+1).
// ============================================================
#define GKT 256
#define GSTAGES (NH / GKT)   // 8

__global__ void __launch_bounds__(128) gateup_kernel(
    const float* __restrict__ x,
    const float* __restrict__ w_gate, const float* __restrict__ w_up)
{
    __shared__ float sw[2][16][GKT];   // 32 KB
    __shared__ float sa[2][8][GKT];    // 16 KB

    const int ch = blockIdx.y;
    if (ch >= d_nchunks) return;
    const int slot0 = d_chunk_slot0[ch];
    const int nc    = d_chunk_nc[ch];
    const int e     = d_chunk_expert[ch];

    const int tid  = threadIdx.x;
    const int warp = tid >> 5;
    const int lane = tid & 31;
    const int i0   = blockIdx.x * 8;

    // staging coords: col4 fixed per thread, rows strided by 2
    const int c4 = tid & 63;
    const int r0 = tid >> 6;   // 0/1

    const float* wsrc[8];
    uint32_t     wdst[8];
    const float* asrc[4];
    uint32_t     adst[4];
#pragma unroll
    for (int j = 0; j < 8; j++) {
        const int r = r0 + 2 * j;     // 0..15
        const float* base = (r < 8)
            ? (w_gate + ((size_t)e * NI + i0 + r) * NH)
            : (w_up   + ((size_t)e * NI + i0 + (r - 8)) * NH);
        wsrc[j] = base + 4 * c4;
        wdst[j] = (uint32_t)__cvta_generic_to_shared(&sw[0][r][4 * c4]);
    }
#pragma unroll
    for (int j = 0; j < 4; j++) {
        const int t = r0 + 2 * j;     // 0..7
        asrc[j] = x + (size_t)d_pair_token[slot0 + t] * NH + 4 * c4;
        adst[j] = (uint32_t)__cvta_generic_to_shared(&sa[0][t][4 * c4]);
    }
    const uint32_t wstride = 16u * GKT * 4u;   // bytes per weight buffer
    const uint32_t astride = 8u * GKT * 4u;

    // prologue: stage 0
#pragma unroll
    for (int j = 0; j < 8; j++) cpa16(wdst[j], wsrc[j]);
#pragma unroll
    for (int j = 0; j < 4; j++) cpa16(adst[j], asrc[j]);
    asm volatile("cp.async.commit_group;");

    unsigned long long ag0[8], ag1[8], au0[8], au1[8];
#pragma unroll
    for (int t = 0; t < 8; t++) { ag0[t] = 0ull; ag1[t] = 0ull; au0[t] = 0ull; au1[t] = 0ull; }

    for (int s = 0; s < GSTAGES; s++) {
        if (s + 1 < GSTAGES) {
            const uint32_t nb = (uint32_t)((s + 1) & 1);
#pragma unroll
            for (int j = 0; j < 8; j++)
                cpa16(wdst[j] + nb * wstride, wsrc[j] + (size_t)(s + 1) * GKT);
#pragma unroll
            for (int j = 0; j < 4; j++)
                cpa16(adst[j] + nb * astride, asrc[j] + (size_t)(s + 1) * GKT);
            asm volatile("cp.async.commit_group;");
            asm volatile("cp.async.wait_group 1;");
        } else {
            asm volatile("cp.async.wait_group 0;");
        }
        __syncthreads();

        const int b = s & 1;
#pragma unroll
        for (int q = 0; q < GKT / 128; q++) {   // 2
            const int ko = 4 * lane + 128 * q;
            const ulonglong2 wg0 = *(const ulonglong2*)&sw[b][2 * warp][ko];
            const ulonglong2 wg1 = *(const ulonglong2*)&sw[b][2 * warp + 1][ko];
            const ulonglong2 wu0 = *(const ulonglong2*)&sw[b][8 + 2 * warp][ko];
            const ulonglong2 wu1 = *(const ulonglong2*)&sw[b][8 + 2 * warp + 1][ko];
#pragma unroll
            for (int t = 0; t < 8; t++) {
                const ulonglong2 av = *(const ulonglong2*)&sa[b][t][ko];
                ag0[t] = fma2(wg0.x, av.x, ag0[t]); ag0[t] = fma2(wg0.y, av.y, ag0[t]);
                ag1[t] = fma2(wg1.x, av.x, ag1[t]); ag1[t] = fma2(wg1.y, av.y, ag1[t]);
                au0[t] = fma2(wu0.x, av.x, au0[t]); au0[t] = fma2(wu0.y, av.y, au0[t]);
                au1[t] = fma2(wu1.x, av.x, au1[t]); au1[t] = fma2(wu1.y, av.y, au1[t]);
            }
        }
        __syncthreads();
    }

    // reduce + SiLU + write: warp owns inter rows i0+2w, i0+2w+1
#pragma unroll
    for (int t = 0; t < 8; t++) {
        const float g0 = wred(ag0[t]);
        const float g1 = wred(ag1[t]);
        const float u0 = wred(au0[t]);
        const float u1 = wred(au1[t]);
        if (lane == 0 && t < nc) {
            float* mo = d_mixed + (size_t)(slot0 + t) * NI + i0 + 2 * warp;
            mo[0] = (g0 / (1.f + expf(-g0))) * u0;
            mo[1] = (g1 / (1.f + expf(-g1))) * u1;
        }
    }
}

// ============================================================
// Kernel 3: down projection.
// Block = one chunk x 16 hidden rows. cp.async double-buffered
// k-tiles (KTILE=128): 16 weight rows + 8 mixed rows per stage.
// Warp computes 4 h-rows x 8 tokens from SMEM.
// ============================================================
#define DKT 128
#define DSTAGES (NI / DKT)   // 11

__global__ void __launch_bounds__(128) down_kernel(const float* __restrict__ w_down)
{
    __shared__ float sw[2][16][DKT];   // 16 KB
    __shared__ float sa[2][8][DKT];    // 8 KB

    const int ch = blockIdx.y;
    if (ch >= d_nchunks) return;
    const int slot0 = d_chunk_slot0[ch];
    const int nc    = d_chunk_nc[ch];
    const int e     = d_chunk_expert[ch];

    const int tid  = threadIdx.x;
    const int warp = tid >> 5;
    const int lane = tid & 31;
    const int h0   = blockIdx.x * 16;

    const int c4 = tid & 31;
    const int r0 = tid >> 5;   // 0..3

    const float* wsrc[4];
    uint32_t     wdst[4];
    const float* asrc[2];
    uint32_t     adst[2];
#pragma unroll
    for (int j = 0; j < 4; j++) {
        const int r = r0 + 4 * j;   // 0..15
        wsrc[j] = w_down + ((size_t)e * NH + h0 + r) * NI + 4 * c4;
        wdst[j] = (uint32_t)__cvta_generic_to_shared(&sw[0][r][4 * c4]);
    }
#pragma unroll
    for (int j = 0; j < 2; j++) {
        const int t = r0 + 4 * j;   // 0..7
        asrc[j] = d_mixed + (size_t)(slot0 + t) * NI + 4 * c4;
        adst[j] = (uint32_t)__cvta_generic_to_shared(&sa[0][t][4 * c4]);
    }
    const uint32_t wstride = 16u * DKT * 4u;
    const uint32_t astride = 8u * DKT * 4u;

#pragma unroll
    for (int j = 0; j < 4; j++) cpa16(wdst[j], wsrc[j]);
#pragma unroll
    for (int j = 0; j < 2; j++) cpa16(adst[j], asrc[j]);
    asm volatile("cp.async.commit_group;");

    unsigned long long a0[8], a1[8], a2[8], a3[8];
#pragma unroll
    for (int t = 0; t < 8; t++) { a0[t] = 0ull; a1[t] = 0ull; a2[t] = 0ull; a3[t] = 0ull; }

    for (int s = 0; s < DSTAGES; s++) {
        if (s + 1 < DSTAGES) {
            const uint32_t nb = (uint32_t)((s + 1) & 1);
#pragma unroll
            for (int j = 0; j < 4; j++)
                cpa16(wdst[j] + nb * wstride, wsrc[j] + (size_t)(s + 1) * DKT);
#pragma unroll
            for (int j = 0; j < 2; j++)
                cpa16(adst[j] + nb * astride, asrc[j] + (size_t)(s + 1) * DKT);
            asm volatile("cp.async.commit_group;");
            asm volatile("cp.async.wait_group 1;");
        } else {
            asm volatile("cp.async.wait_group 0;");
        }
        __syncthreads();

        const int b = s & 1;
        const int ko = 4 * lane;
        const ulonglong2 w0 = *(const ulonglong2*)&sw[b][4 * warp][ko];
        const ulonglong2 w1 = *(const ulonglong2*)&sw[b][4 * warp + 1][ko];
        const ulonglong2 w2 = *(const ulonglong2*)&sw[b][4 * warp + 2][ko];
        const ulonglong2 w3 = *(const ulonglong2*)&sw[b][4 * warp + 3][ko];
#pragma unroll
        for (int t = 0; t < 8; t++) {
            const ulonglong2 av = *(const ulonglong2*)&sa[b][t][ko];
            a0[t] = fma2(w0.x, av.x, a0[t]); a0[t] = fma2(w0.y, av.y, a0[t]);
            a1[t] = fma2(w1.x, av.x, a1[t]); a1[t] = fma2(w1.y, av.y, a1[t]);
            a2[t] = fma2(w2.x, av.x, a2[t]); a2[t] = fma2(w2.y, av.y, a2[t]);
            a3[t] = fma2(w3.x, av.x, a3[t]); a3[t] = fma2(w3.y, av.y, a3[t]);
        }
        __syncthreads();
    }

#pragma unroll
    for (int t = 0; t < 8; t++) {
        const float v0 = wred(a0[t]);
        const float v1 = wred(a1[t]);
        const float v2 = wred(a2[t]);
        const float v3 = wred(a3[t]);
        if (lane == 0 && t < nc) {
            float* po = d_pair_out + (size_t)(slot0 + t) * NH + h0 + 4 * warp;
            po[0] = v0; po[1] = v1; po[2] = v2; po[3] = v3;
        }
    }
}

// ============================================================
// Kernel 4: weighted combine of the 4 routed pair outputs.
// ============================================================
__global__ void combine_kernel(float* __restrict__ out)
{
    const int idx = blockIdx.x * blockDim.x + threadIdx.x;  // [0, NT*NH)
    const int t = idx / NH;
    const int h = idx - t * NH;
    float s = 0.f;
#pragma unroll
    for (int k = 0; k < NK; k++) {
        const int p = d_pair_idx[t * NK + k];
        s = fmaf(d_topk_w[t * NK + k], d_pair_out[(size_t)p * NH + h], s);
    }
    out[idx] = s;
}

// ============================================================
extern "C" void kernel_launch(void* const* d_in, const int* in_sizes, int n_in,
                              void* d_out, int out_size)
{
    const float* x      = (const float*)d_in[0];
    const float* logits = (const float*)d_in[1];
    const float* wg     = (const float*)d_in[2];
    const float* wu     = (const float*)d_in[3];
    const float* wd     = (const float*)d_in[4];
    float* out = (float*)d_out;

    route_kernel<<<1, NT>>>(logits);
    gateup_kernel<<<dim3(NI / 8, MAXCHUNK), 128>>>(x, wg, wu);
    down_kernel<<<dim3(NH / 16, MAXCHUNK), 128>>>(wd);
    combine_kernel<<<(NT * NH) / 256, 256>>>(out);
}

// round 17
// speedup vs baseline: 1.2245x; 1.0192x over previous
#include <cuda_runtime.h>
#include <math.h>
#include <stdint.h>

#define NT 64
#define NH 2048
#define NI 1408
#define NE 32
#define NK 4
#define NPAIR (NT * NK)
#define MAXSLOT (NPAIR + NE * 7)   // per-expert padding to multiple of 8
#define MAXCHUNK 64

// ---- scratch (device globals: no allocation allowed) ----
__device__ int   d_nchunks;
__device__ int   d_chunk_slot0[MAXCHUNK];   // chunk -> first slot
__device__ int   d_chunk_nc[MAXCHUNK];      // chunk -> live token count (1..8)
__device__ int   d_chunk_expert[MAXCHUNK];  // chunk -> expert
__device__ int   d_pair_token[MAXSLOT];     // slot -> token (pads -> 0)
__device__ int   d_pair_idx[NT * NK];       // (token,k) -> slot
__device__ float d_topk_w[NT * NK];         // routing weights
__device__ float d_mixed[MAXSLOT * NI];     // silu(g)*u per slot
__device__ float d_pair_out[MAXSLOT * NH];  // down output per slot

// ---- packed f32x2 helpers (FFMA2: PTX-only on sm_103a) ----
__device__ __forceinline__ unsigned long long fma2(unsigned long long a,
                                                   unsigned long long b,
                                                   unsigned long long c) {
    unsigned long long d;
    asm("fma.rn.f32x2 %0, %1, %2, %3;" : "=l"(d) : "l"(a), "l"(b), "l"(c));
    return d;
}
__device__ __forceinline__ unsigned long long add2(unsigned long long a,
                                                   unsigned long long b) {
    unsigned long long d;
    asm("add.rn.f32x2 %0, %1, %2;" : "=l"(d) : "l"(a), "l"(b));
    return d;
}
// warp-reduce packed accumulator, fold (k,k+1) halves at the end
__device__ __forceinline__ float wred(unsigned long long v) {
#pragma unroll
    for (int o = 16; o > 0; o >>= 1)
        v = add2(v, __shfl_down_sync(0xFFFFFFFFu, v, o));
    float lo, hi;
    asm("mov.b64 {%0, %1}, %2;" : "=f"(lo), "=f"(hi) : "l"(v));
    return lo + hi;
}
// 16-byte async copy global -> shared (no register staging)
__device__ __forceinline__ void cpa16(uint32_t dst, const float* src) {
    asm volatile("cp.async.cg.shared.global [%0], [%1], 16;" :: "r"(dst), "l"(src));
}
#define CP_COMMIT() asm volatile("cp.async.commit_group;")
// tail-aware wait: guarantee stage s is complete given stages committed so far
#define CP_WAIT_STAGE(s, STAGES)                                   \
    do {                                                           \
        if ((s) + 1 == (STAGES))      asm volatile("cp.async.wait_group 0;"); \
        else if ((s) + 2 == (STAGES)) asm volatile("cp.async.wait_group 1;"); \
        else                          asm volatile("cp.async.wait_group 2;"); \
    } while (0)

// ============================================================
// Kernel 1: routing + chunk table. One block, one thread/token.
// ============================================================
__global__ void route_kernel(const float* __restrict__ logits) {
    __shared__ int s_count[NE];
    __shared__ int s_start[NE];
    __shared__ int s_slot[NE];
    const int t = threadIdx.x;

    if (t < NE) { s_count[t] = 0; s_slot[t] = 0; }
    __syncthreads();

    float v[NE];
#pragma unroll
    for (int e = 0; e < NE; e++) v[e] = logits[t * NE + e];

    int ids[NK];
    float vals[NK];
#pragma unroll
    for (int k = 0; k < NK; k++) {
        int best = 0;
        float bv = -1e30f;
#pragma unroll
        for (int e = 0; e < NE; e++) {
            if (v[e] > bv) { bv = v[e]; best = e; }  // strict > : lowest index wins ties
        }
        ids[k] = best;
        vals[k] = bv;
        v[best] = -1e30f;
    }

    float m = vals[0];
    float w[NK];
    float s = 0.f;
#pragma unroll
    for (int k = 0; k < NK; k++) { w[k] = expf(vals[k] - m); s += w[k]; }
    float inv = 1.f / s;
#pragma unroll
    for (int k = 0; k < NK; k++) d_topk_w[t * NK + k] = w[k] * inv;

#pragma unroll
    for (int k = 0; k < NK; k++) atomicAdd(&s_count[ids[k]], 1);
    __syncthreads();

    if (t == 0) {
        int off = 0;
        int nch = 0;
        for (int e = 0; e < NE; e++) {
            s_start[e] = off;
            const int cnt = s_count[e];
            for (int c = 0; c < cnt; c += 8) {
                d_chunk_slot0[nch] = off + c;
                d_chunk_nc[nch] = (cnt - c < 8) ? (cnt - c) : 8;
                d_chunk_expert[nch] = e;
                nch++;
            }
            off += (cnt + 7) & ~7;   // pad each expert region to multiple of 8
        }
        d_nchunks = nch;
    }
    __syncthreads();

#pragma unroll
    for (int k = 0; k < NK; k++) {
        int slot = atomicAdd(&s_slot[ids[k]], 1);
        int p = s_start[ids[k]] + slot;
        d_pair_token[p] = t;
        d_pair_idx[t * NK + k] = p;
    }
    if (t < NE) {
        const int cnt = s_count[t];
        const int padded = (cnt + 7) & ~7;
        for (int p = cnt; p < padded; p++)      // pad slots -> token 0
            d_pair_token[s_start[t] + p] = 0;
    }
}

// ============================================================
// Kernel 2: gate/up matvecs + SiLU.
// Block = one chunk x 8 inter rows. 4-buffer cp.async ring,
// prefetch distance 3, ONE barrier per stage (buffer written
// (s+3)%4 is distinct from read s%4 and in-flight s+1,s+2).
// Warp: 2 gate + 2 up rows x 8 tokens; FFMA2 halves=(k,k+1).
// ============================================================
#define GKT 128
#define GST (NH / GKT)   // 16

__global__ void __launch_bounds__(128) gateup_kernel(
    const float* __restrict__ x,
    const float* __restrict__ w_gate, const float* __restrict__ w_up)
{
    __shared__ float sw[4][16][GKT];   // 32 KB
    __shared__ float sa[4][8][GKT];    // 16 KB

    const int ch = blockIdx.y;
    if (ch >= d_nchunks) return;
    const int slot0 = d_chunk_slot0[ch];
    const int nc    = d_chunk_nc[ch];
    const int e     = d_chunk_expert[ch];

    const int tid  = threadIdx.x;
    const int warp = tid >> 5;
    const int lane = tid & 31;
    const int i0   = blockIdx.x * 8;

    // staging coords: 16 w-rows x 32 float4 = 512 -> 4/thread; 8 a-rows x 32 = 256 -> 2/thread
    const int c4 = tid & 31;   // float4 col 0..31
    const int r0 = tid >> 5;   // 0..3

    const float* wsrc[4];
    uint32_t     wdst[4];
    const float* asrc[2];
    uint32_t     adst[2];
#pragma unroll
    for (int j = 0; j < 4; j++) {
        const int r = r0 + 4 * j;   // 0..15
        const float* base = (r < 8)
            ? (w_gate + ((size_t)e * NI + i0 + r) * NH)
            : (w_up   + ((size_t)e * NI + i0 + (r - 8)) * NH);
        wsrc[j] = base + 4 * c4;
        wdst[j] = (uint32_t)__cvta_generic_to_shared(&sw[0][r][4 * c4]);
    }
#pragma unroll
    for (int j = 0; j < 2; j++) {
        const int t = r0 + 4 * j;   // 0..7
        asrc[j] = x + (size_t)d_pair_token[slot0 + t] * NH + 4 * c4;
        adst[j] = (uint32_t)__cvta_generic_to_shared(&sa[0][t][4 * c4]);
    }
    const uint32_t wstride = 16u * GKT * 4u;
    const uint32_t astride = 8u * GKT * 4u;

    // prologue: issue stages 0..2
#pragma unroll
    for (int ps = 0; ps < 3; ps++) {
        const uint32_t b = (uint32_t)ps;
#pragma unroll
        for (int j = 0; j < 4; j++) cpa16(wdst[j] + b * wstride, wsrc[j] + (size_t)ps * GKT);
#pragma unroll
        for (int j = 0; j < 2; j++) cpa16(adst[j] + b * astride, asrc[j] + (size_t)ps * GKT);
        CP_COMMIT();
    }

    unsigned long long ag0[8], ag1[8], au0[8], au1[8];
#pragma unroll
    for (int t = 0; t < 8; t++) { ag0[t] = 0ull; ag1[t] = 0ull; au0[t] = 0ull; au1[t] = 0ull; }

    for (int s = 0; s < GST; s++) {
        CP_WAIT_STAGE(s, GST);
        __syncthreads();                     // the ONLY barrier per stage

        if (s + 3 < GST) {                   // prefetch stage s+3 into buffer (s+3)&3
            const uint32_t nb = (uint32_t)((s + 3) & 3);
#pragma unroll
            for (int j = 0; j < 4; j++) cpa16(wdst[j] + nb * wstride, wsrc[j] + (size_t)(s + 3) * GKT);
#pragma unroll
            for (int j = 0; j < 2; j++) cpa16(adst[j] + nb * astride, asrc[j] + (size_t)(s + 3) * GKT);
            CP_COMMIT();
        }

        const int b = s & 3;
        const int ko = 4 * lane;
        const ulonglong2 wg0 = *(const ulonglong2*)&sw[b][2 * warp][ko];
        const ulonglong2 wg1 = *(const ulonglong2*)&sw[b][2 * warp + 1][ko];
        const ulonglong2 wu0 = *(const ulonglong2*)&sw[b][8 + 2 * warp][ko];
        const ulonglong2 wu1 = *(const ulonglong2*)&sw[b][8 + 2 * warp + 1][ko];
#pragma unroll
        for (int t = 0; t < 8; t++) {
            const ulonglong2 av = *(const ulonglong2*)&sa[b][t][ko];
            ag0[t] = fma2(wg0.x, av.x, ag0[t]); ag0[t] = fma2(wg0.y, av.y, ag0[t]);
            ag1[t] = fma2(wg1.x, av.x, ag1[t]); ag1[t] = fma2(wg1.y, av.y, ag1[t]);
            au0[t] = fma2(wu0.x, av.x, au0[t]); au0[t] = fma2(wu0.y, av.y, au0[t]);
            au1[t] = fma2(wu1.x, av.x, au1[t]); au1[t] = fma2(wu1.y, av.y, au1[t]);
        }
    }

    // reduce + SiLU + write: warp owns inter rows i0+2w, i0+2w+1
#pragma unroll
    for (int t = 0; t < 8; t++) {
        const float g0 = wred(ag0[t]);
        const float g1 = wred(ag1[t]);
        const float u0 = wred(au0[t]);
        const float u1 = wred(au1[t]);
        if (lane == 0 && t < nc) {
            float* mo = d_mixed + (size_t)(slot0 + t) * NI + i0 + 2 * warp;
            mo[0] = (g0 / (1.f + expf(-g0))) * u0;
            mo[1] = (g1 / (1.f + expf(-g1))) * u1;
        }
    }
}

// ============================================================
// Kernel 3: down projection.
// Block = one chunk x 16 hidden rows. Same 4-buffer ring,
// prefetch distance 3, one barrier per stage.
// Warp: 4 h-rows x 8 tokens.
// ============================================================
#define DKT 128
#define DST (NI / DKT)   // 11

__global__ void __launch_bounds__(128) down_kernel(const float* __restrict__ w_down)
{
    __shared__ float sw[4][16][DKT];   // 32 KB
    __shared__ float sa[4][8][DKT];    // 16 KB

    const int ch = blockIdx.y;
    if (ch >= d_nchunks) return;
    const int slot0 = d_chunk_slot0[ch];
    const int nc    = d_chunk_nc[ch];
    const int e     = d_chunk_expert[ch];

    const int tid  = threadIdx.x;
    const int warp = tid >> 5;
    const int lane = tid & 31;
    const int h0   = blockIdx.x * 16;

    const int c4 = tid & 31;
    const int r0 = tid >> 5;   // 0..3

    const float* wsrc[4];
    uint32_t     wdst[4];
    const float* asrc[2];
    uint32_t     adst[2];
#pragma unroll
    for (int j = 0; j < 4; j++) {
        const int r = r0 + 4 * j;   // 0..15
        wsrc[j] = w_down + ((size_t)e * NH + h0 + r) * NI + 4 * c4;
        wdst[j] = (uint32_t)__cvta_generic_to_shared(&sw[0][r][4 * c4]);
    }
#pragma unroll
    for (int j = 0; j < 2; j++) {
        const int t = r0 + 4 * j;   // 0..7
        asrc[j] = d_mixed + (size_t)(slot0 + t) * NI + 4 * c4;
        adst[j] = (uint32_t)__cvta_generic_to_shared(&sa[0][t][4 * c4]);
    }
    const uint32_t wstride = 16u * DKT * 4u;
    const uint32_t astride = 8u * DKT * 4u;

#pragma unroll
    for (int ps = 0; ps < 3; ps++) {
        const uint32_t b = (uint32_t)ps;
#pragma unroll
        for (int j = 0; j < 4; j++) cpa16(wdst[j] + b * wstride, wsrc[j] + (size_t)ps * DKT);
#pragma unroll
        for (int j = 0; j < 2; j++) cpa16(adst[j] + b * astride, asrc[j] + (size_t)ps * DKT);
        CP_COMMIT();
    }

    unsigned long long a0[8], a1[8], a2[8], a3[8];
#pragma unroll
    for (int t = 0; t < 8; t++) { a0[t] = 0ull; a1[t] = 0ull; a2[t] = 0ull; a3[t] = 0ull; }

    for (int s = 0; s < DST; s++) {
        CP_WAIT_STAGE(s, DST);
        __syncthreads();

        if (s + 3 < DST) {
            const uint32_t nb = (uint32_t)((s + 3) & 3);
#pragma unroll
            for (int j = 0; j < 4; j++) cpa16(wdst[j] + nb * wstride, wsrc[j] + (size_t)(s + 3) * DKT);
#pragma unroll
            for (int j = 0; j < 2; j++) cpa16(adst[j] + nb * astride, asrc[j] + (size_t)(s + 3) * DKT);
            CP_COMMIT();
        }

        const int b = s & 3;
        const int ko = 4 * lane;
        const ulonglong2 w0 = *(const ulonglong2*)&sw[b][4 * warp][ko];
        const ulonglong2 w1 = *(const ulonglong2*)&sw[b][4 * warp + 1][ko];
        const ulonglong2 w2 = *(const ulonglong2*)&sw[b][4 * warp + 2][ko];
        const ulonglong2 w3 = *(const ulonglong2*)&sw[b][4 * warp + 3][ko];
#pragma unroll
        for (int t = 0; t < 8; t++) {
            const ulonglong2 av = *(const ulonglong2*)&sa[b][t][ko];
            a0[t] = fma2(w0.x, av.x, a0[t]); a0[t] = fma2(w0.y, av.y, a0[t]);
            a1[t] = fma2(w1.x, av.x, a1[t]); a1[t] = fma2(w1.y, av.y, a1[t]);
            a2[t] = fma2(w2.x, av.x, a2[t]); a2[t] = fma2(w2.y, av.y, a2[t]);
            a3[t] = fma2(w3.x, av.x, a3[t]); a3[t] = fma2(w3.y, av.y, a3[t]);
        }
    }

#pragma unroll
    for (int t = 0; t < 8; t++) {
        const float v0 = wred(a0[t]);
        const float v1 = wred(a1[t]);
        const float v2 = wred(a2[t]);
        const float v3 = wred(a3[t]);
        if (lane == 0 && t < nc) {
            float* po = d_pair_out + (size_t)(slot0 + t) * NH + h0 + 4 * warp;
            po[0] = v0; po[1] = v1; po[2] = v2; po[3] = v3;
        }
    }
}

// ============================================================
// Kernel 4: weighted combine of the 4 routed pair outputs.
// ============================================================
__global__ void combine_kernel(float* __restrict__ out)
{
    const int idx = blockIdx.x * blockDim.x + threadIdx.x;  // [0, NT*NH)
    const int t = idx / NH;
    const int h = idx - t * NH;
    float s = 0.f;
#pragma unroll
    for (int k = 0; k < NK; k++) {
        const int p = d_pair_idx[t * NK + k];
        s = fmaf(d_topk_w[t * NK + k], d_pair_out[(size_t)p * NH + h], s);
    }
    out[idx] = s;
}

// ============================================================
extern "C" void kernel_launch(void* const* d_in, const int* in_sizes, int n_in,
                              void* d_out, int out_size)
{
    const float* x      = (const float*)d_in[0];
    const float* logits = (const float*)d_in[1];
    const float* wg     = (const float*)d_in[2];
    const float* wu     = (const float*)d_in[3];
    const float* wd     = (const float*)d_in[4];
    float* out = (float*)d_out;

    route_kernel<<<1, NT>>>(logits);
    gateup_kernel<<<dim3(NI / 8, MAXCHUNK), 128>>>(x, wg, wu);
    down_kernel<<<dim3(NH / 16, MAXCHUNK), 128>>>(wd);
    combine_kernel<<<(NT * NH) / 256, 256>>>(out);
}